// round 2
// baseline (speedup 1.0000x reference)
#include <cuda_runtime.h>
#include <math.h>

#define LSEQ 4680
#define DIM  1536
#define NH   12
#define HD   128

// Scratch (device-global arrays: allocation-free per harness rules)
__device__ float g_q[LSEQ * DIM];
__device__ float g_k[LSEQ * DIM];
__device__ float g_v[LSEQ * DIM];
__device__ float g_o[LSEQ * DIM];

// ---------------------------------------------------------------------------
// C[M,N] = A[M,K] @ W[N,K]^T + bias[N]   (both operands K-contiguous, "NT")
// 64x64 tile, BK=16, 256 threads, 4x4 micro-tile, float4 smem reads.
// ---------------------------------------------------------------------------
__global__ __launch_bounds__(256)
void gemm_nt_bias(const float* __restrict__ A, const float* __restrict__ W,
                  const float* __restrict__ bias, float* __restrict__ C,
                  int M, int N, int K)
{
    const int BM = 64, BK = 16;
    __shared__ float As[16][68];   // [k][m], pad keeps float4 alignment (272B rows)
    __shared__ float Ws[16][68];   // [k][n]
    int tid = threadIdx.x;
    int tx = tid & 15, ty = tid >> 4;
    int row0 = blockIdx.y * BM;
    int col0 = blockIdx.x * BM;

    float acc[4][4];
#pragma unroll
    for (int i = 0; i < 4; i++)
#pragma unroll
        for (int j = 0; j < 4; j++) acc[i][j] = 0.f;

    for (int k0 = 0; k0 < K; k0 += BK) {
#pragma unroll
        for (int i = 0; i < 4; i++) {
            int r  = ty + i * 16;          // 0..63
            int gr = row0 + r;
            As[tx][r] = (gr < M) ? A[(size_t)gr * K + k0 + tx] : 0.f;
            Ws[tx][r] = W[(size_t)(col0 + r) * K + k0 + tx];   // N always mult of 64
        }
        __syncthreads();
#pragma unroll
        for (int kq = 0; kq < BK; kq++) {
            float4 a4 = *(const float4*)&As[kq][ty * 4];
            float4 b4 = *(const float4*)&Ws[kq][tx * 4];
            float av[4] = {a4.x, a4.y, a4.z, a4.w};
            float bv[4] = {b4.x, b4.y, b4.z, b4.w};
#pragma unroll
            for (int i = 0; i < 4; i++)
#pragma unroll
                for (int j = 0; j < 4; j++)
                    acc[i][j] += av[i] * bv[j];
        }
        __syncthreads();
    }
#pragma unroll
    for (int i = 0; i < 4; i++) {
        int gr = row0 + ty * 4 + i;
        if (gr < M) {
#pragma unroll
            for (int j = 0; j < 4; j++) {
                int gc = col0 + tx * 4 + j;
                C[(size_t)gr * N + gc] = acc[i][j] + bias[gc];
            }
        }
    }
}

// ---------------------------------------------------------------------------
// Fused RMSNorm (over full dim=1536) + RoPE (per head, d=128, c=64 pairs).
// One block per sequence position, in-place on q and k.
// ---------------------------------------------------------------------------
__global__ __launch_bounds__(256)
void norm_rope(float* __restrict__ q, float* __restrict__ k,
               const float* __restrict__ gq, const float* __restrict__ gk,
               const float* __restrict__ freqs,
               const int* __restrict__ p_h, const int* __restrict__ p_w,
               const int* __restrict__ p_sf)
{
    int l = blockIdx.x;
    int tid = threadIdx.x;
    __shared__ float sq[DIM], sk[DIM];
    __shared__ float redq[256], redk[256];

    size_t base = (size_t)l * DIM;
    float ssq = 0.f, ssk = 0.f;
    for (int i = tid; i < DIM; i += 256) {
        float a = q[base + i], b = k[base + i];
        sq[i] = a; sk[i] = b;
        ssq += a * a; ssk += b * b;
    }
    redq[tid] = ssq; redk[tid] = ssk;
    __syncthreads();
    for (int s = 128; s > 0; s >>= 1) {
        if (tid < s) { redq[tid] += redq[tid + s]; redk[tid] += redk[tid + s]; }
        __syncthreads();
    }
    float rq = rsqrtf(redq[0] * (1.f / DIM) + 1e-6f);
    float rk = rsqrtf(redk[0] * (1.f / DIM) + 1e-6f);

    int h = *p_h, w = *p_w, sf = *p_sf;
    int hw = h * w;
    int fr = l / hw, rem = l - fr * hw;
    int rr = rem / w, cc = rem - rr * w;
    const int c  = HD / 2;        // 64
    const int c1 = c / 3;         // 21
    const int c0 = c - 2 * c1;    // 22

    for (int p = tid; p < DIM / 2; p += 256) {
        int head = p >> 6;        // pair index within head: 0..63
        int i    = p & 63;
        int pos  = (i < c0) ? (sf + fr) : ((i < c0 + c1) ? rr : cc);
        float ang = freqs[pos * c + i];
        float cs = cosf(ang), sn = sinf(ang);
        int idx = head * HD + 2 * i;

        float qre = sq[idx] * rq * gq[idx];
        float qim = sq[idx + 1] * rq * gq[idx + 1];
        q[base + idx]     = qre * cs - qim * sn;
        q[base + idx + 1] = qre * sn + qim * cs;

        float kre = sk[idx] * rk * gk[idx];
        float kim = sk[idx + 1] * rk * gk[idx + 1];
        k[base + idx]     = kre * cs - kim * sn;
        k[base + idx + 1] = kre * sn + kim * cs;
    }
}

// ---------------------------------------------------------------------------
// Flash attention, frame-causal mask.
// Block = (64 queries) x (1 head). 128 threads: 2 threads per query row,
// each owning a 64-dim half. 32-key tiles staged in smem.
// ---------------------------------------------------------------------------
__global__ __launch_bounds__(128)
void attn(const float* __restrict__ q, const float* __restrict__ k,
          const float* __restrict__ v, float* __restrict__ o,
          const int* __restrict__ p_h, const int* __restrict__ p_w,
          const int* __restrict__ p_local, const int* __restrict__ p_sink)
{
    const int BQ = 64, BKV = 32;
    int qb = blockIdx.x, hd = blockIdx.y;
    int tid = threadIdx.x;
    int qrow = tid >> 1, half = tid & 1;
    int lq = qb * BQ + qrow;
    bool active = lq < LSEQ;
    int lql = active ? lq : (LSEQ - 1);

    int hw = (*p_h) * (*p_w);
    int local = *p_local, sink = *p_sink;
    int fi = lql / hw;

    float qreg[64];
    const float scl = rsqrtf((float)HD);
    {
        const float* qp = q + (size_t)lql * DIM + hd * HD + half * 64;
#pragma unroll
        for (int i = 0; i < 64; i++) qreg[i] = qp[i] * scl;
    }

    float m = -1e30f, lsum = 0.f;
    float acc[64];
#pragma unroll
    for (int i = 0; i < 64; i++) acc[i] = 0.f;

    __shared__ float Ks[BKV][HD];
    __shared__ float Vs[BKV][HD];

    int last_q = min(qb * BQ + BQ - 1, LSEQ - 1);
    int kend = (last_q / hw + 1) * hw;   // block-causal upper bound for this tile

    for (int kb = 0; kb < kend; kb += BKV) {
        __syncthreads();
        for (int idx = tid; idx < BKV * HD; idx += 128) {
            int r = idx >> 7, cidx = idx & 127;
            int lk = kb + r;
            if (lk < LSEQ) {
                size_t off = (size_t)lk * DIM + hd * HD + cidx;
                Ks[r][cidx] = k[off];
                Vs[r][cidx] = v[off];
            } else {
                Ks[r][cidx] = 0.f; Vs[r][cidx] = 0.f;
            }
        }
        __syncthreads();

        float s[BKV];
#pragma unroll
        for (int j = 0; j < BKV; j++) {
            const float4* kr = (const float4*)&Ks[j][half * 64];
            float s0 = 0.f, s1 = 0.f, s2 = 0.f, s3 = 0.f;
#pragma unroll
            for (int i4 = 0; i4 < 16; i4++) {
                float4 kv = kr[i4];
                s0 += qreg[i4 * 4 + 0] * kv.x;
                s1 += qreg[i4 * 4 + 1] * kv.y;
                s2 += qreg[i4 * 4 + 2] * kv.z;
                s3 += qreg[i4 * 4 + 3] * kv.w;
            }
            s[j] = (s0 + s1) + (s2 + s3);
        }
#pragma unroll
        for (int j = 0; j < BKV; j++)
            s[j] += __shfl_xor_sync(0xffffffffu, s[j], 1);

        float tmax = -1e30f;
#pragma unroll
        for (int j = 0; j < BKV; j++) {
            int lk = kb + j;
            int fj = lk / hw;
            bool ok = active && (lk < LSEQ) && (fj <= fi) &&
                      (((fi - fj) < local) || (fj < sink));
            s[j] = ok ? s[j] : -1e30f;
            tmax = fmaxf(tmax, s[j]);
        }
        if (tmax > -1e29f) {   // per-thread predicate; no barriers inside
            float mnew = fmaxf(m, tmax);
            float corr = __expf(m - mnew);
            lsum *= corr;
#pragma unroll
            for (int i = 0; i < 64; i++) acc[i] *= corr;
#pragma unroll
            for (int j = 0; j < BKV; j++) {
                float pj = __expf(s[j] - mnew);
                lsum += pj;
                s[j] = pj;
            }
#pragma unroll
            for (int j = 0; j < BKV; j++) {
                float pj = s[j];
                const float4* vr = (const float4*)&Vs[j][half * 64];
#pragma unroll
                for (int i4 = 0; i4 < 16; i4++) {
                    float4 vv = vr[i4];
                    acc[i4 * 4 + 0] += pj * vv.x;
                    acc[i4 * 4 + 1] += pj * vv.y;
                    acc[i4 * 4 + 2] += pj * vv.z;
                    acc[i4 * 4 + 3] += pj * vv.w;
                }
            }
            m = mnew;
        }
    }

    if (active) {
        float inv = 1.f / lsum;
        float* op = o + (size_t)lq * DIM + hd * HD + half * 64;
#pragma unroll
        for (int i = 0; i < 64; i++) op[i] = acc[i] * inv;
    }
}

// ---------------------------------------------------------------------------
extern "C" void kernel_launch(void* const* d_in, const int* in_sizes, int n_in,
                              void* d_out, int out_size)
{
    const float* x     = (const float*)d_in[0];
    const float* freqs = (const float*)d_in[1];
    const float* Wq    = (const float*)d_in[2];
    const float* bq    = (const float*)d_in[3];
    const float* Wk    = (const float*)d_in[4];
    const float* bk    = (const float*)d_in[5];
    const float* Wv    = (const float*)d_in[6];
    const float* bv    = (const float*)d_in[7];
    const float* Wo    = (const float*)d_in[8];
    const float* bo    = (const float*)d_in[9];
    const float* gq    = (const float*)d_in[10];
    const float* gk    = (const float*)d_in[11];
    const int* p_h     = (const int*)d_in[13];
    const int* p_w     = (const int*)d_in[14];
    const int* p_local = (const int*)d_in[16];
    const int* p_sink  = (const int*)d_in[17];
    const int* p_sf    = (const int*)d_in[18];
    float* out = (float*)d_out;
    (void)in_sizes; (void)n_in; (void)out_size;

    float *pq, *pk, *pv, *po;
    cudaGetSymbolAddress((void**)&pq, g_q);
    cudaGetSymbolAddress((void**)&pk, g_k);
    cudaGetSymbolAddress((void**)&pv, g_v);
    cudaGetSymbolAddress((void**)&po, g_o);

    dim3 gdim(DIM / 64, (LSEQ + 63) / 64);
    gemm_nt_bias<<<gdim, 256>>>(x, Wq, bq, pq, LSEQ, DIM, DIM);
    gemm_nt_bias<<<gdim, 256>>>(x, Wk, bk, pk, LSEQ, DIM, DIM);
    gemm_nt_bias<<<gdim, 256>>>(x, Wv, bv, pv, LSEQ, DIM, DIM);
    norm_rope<<<LSEQ, 256>>>(pq, pk, gq, gk, freqs, p_h, p_w, p_sf);
    attn<<<dim3((LSEQ + 63) / 64, NH), 128>>>(pq, pk, pv, po, p_h, p_w, p_local, p_sink);
    gemm_nt_bias<<<gdim, 256>>>(po, Wo, bo, out, LSEQ, DIM, DIM);
}

// round 6
// speedup vs baseline: 1.2380x; 1.2380x over previous
#include <cuda_runtime.h>
#include <cuda_fp16.h>
#include <cstdint>
#include <math.h>

#define LSEQ 4680
#define DIM  1536
#define NH   12
#define HD   128

// fp32 scratch
__device__ float g_q[LSEQ * DIM];
__device__ float g_k[LSEQ * DIM];
__device__ float g_v[LSEQ * DIM];
__device__ float g_o[LSEQ * DIM];

// split fp16 operands (16B alignment required for cp.async)
__device__ __align__(256) __half g_xhi[LSEQ * DIM];
__device__ __align__(256) __half g_xlo[LSEQ * DIM];
__device__ __align__(256) __half g_ohi[LSEQ * DIM];
__device__ __align__(256) __half g_olo[LSEQ * DIM];
__device__ __align__(256) __half g_wqhi[DIM * DIM];
__device__ __align__(256) __half g_wqlo[DIM * DIM];
__device__ __align__(256) __half g_wkhi[DIM * DIM];
__device__ __align__(256) __half g_wklo[DIM * DIM];
__device__ __align__(256) __half g_wvhi[DIM * DIM];
__device__ __align__(256) __half g_wvlo[DIM * DIM];
__device__ __align__(256) __half g_wohi[DIM * DIM];
__device__ __align__(256) __half g_wolo[DIM * DIM];

// ---------------------------------------------------------------------------
// fp32 -> fp16 (hi, lo) split:  a = hi + lo + O(2^-22 * |a|)
// ---------------------------------------------------------------------------
__global__ __launch_bounds__(256)
void split_kern(const float* __restrict__ in, __half* __restrict__ hi,
                __half* __restrict__ lo, int n)
{
    int i = blockIdx.x * 256 + threadIdx.x;
    if (i < n) {
        float a = in[i];
        __half h = __float2half_rn(a);
        hi[i] = h;
        lo[i] = __float2half_rn(a - __half2float(h));
    }
}

// ---------------------------------------------------------------------------
// mma.sync helpers
// ---------------------------------------------------------------------------
__device__ __forceinline__ void ldsm4(uint32_t a, uint32_t& r0, uint32_t& r1,
                                      uint32_t& r2, uint32_t& r3)
{
    asm volatile("ldmatrix.sync.aligned.m8n8.x4.shared.b16 {%0,%1,%2,%3},[%4];\n"
                 : "=r"(r0), "=r"(r1), "=r"(r2), "=r"(r3) : "r"(a));
}
__device__ __forceinline__ void mma16816(float* c, const uint32_t* a, const uint32_t* b)
{
    asm volatile("mma.sync.aligned.m16n8k16.row.col.f32.f16.f16.f32 "
                 "{%0,%1,%2,%3},{%4,%5,%6,%7},{%8,%9},{%0,%1,%2,%3};\n"
                 : "+f"(c[0]), "+f"(c[1]), "+f"(c[2]), "+f"(c[3])
                 : "r"(a[0]), "r"(a[1]), "r"(a[2]), "r"(a[3]), "r"(b[0]), "r"(b[1]));
}
__device__ __forceinline__ void cp16(uint32_t dst, const void* src)
{
    asm volatile("cp.async.cg.shared.global [%0],[%1],16;\n" :: "r"(dst), "l"(src));
}

// ---------------------------------------------------------------------------
// C[M,N] = A[M,K] @ B[N,K]^T + bias, split-fp16 tensor-core (3-term).
// Block 128x128, BK=32, 8 warps (warp tile 64x32), cp.async double buffer.
// smem: 2 stages x 4 matrices (Ahi,Alo,Bhi,Blo) x 128 rows x 64B = 64KB.
// XOR swizzle: phys_chunk = chunk ^ ((row>>1)&3)  (conflict-free ldmatrix).
// ---------------------------------------------------------------------------
__global__ __launch_bounds__(256, 2)
void gemm_mma(const __half* __restrict__ Ahi, const __half* __restrict__ Alo,
              const __half* __restrict__ Bhi, const __half* __restrict__ Blo,
              const float* __restrict__ bias, float* __restrict__ C, int M)
{
    const int N = DIM, K = DIM;
    extern __shared__ char smbuf[];
    uint32_t sbase = (uint32_t)__cvta_generic_to_shared(smbuf);
    int tid = threadIdx.x;
    int lane = tid & 31, warp = tid >> 5;
    int wm = warp & 1, wn = warp >> 1;          // warp grid 2 x 4
    int row0 = blockIdx.y * 128, col0 = blockIdx.x * 128;

    float acc[4][4][4];
#pragma unroll
    for (int mt = 0; mt < 4; mt++)
#pragma unroll
        for (int nt = 0; nt < 4; nt++)
#pragma unroll
            for (int i = 0; i < 4; i++) acc[mt][nt][i] = 0.f;

    // per-thread load coords (512 chunks of 16B per matrix per stage)
    int ld_row0 = tid >> 2, ld_ch0 = tid & 3;            // chunk 0..3 within 64B row
    int ld_row1 = (tid + 256) >> 2, ld_ch1 = tid & 3;

#define LOAD_STAGE(s, kt)                                                          \
    do {                                                                           \
        int k0 = (kt) * 32;                                                        \
        uint32_t st = sbase + (s) * 32768;                                         \
        {                                                                          \
            int row = ld_row0, ch = ld_ch0;                                        \
            uint32_t off = row * 64 + ((ch ^ ((row >> 1) & 3)) << 4);              \
            int gr = row0 + row; if (gr > M - 1) gr = M - 1;                       \
            size_t aoff = (size_t)gr * K + k0 + ch * 8;                            \
            size_t boff = (size_t)(col0 + row) * K + k0 + ch * 8;                  \
            cp16(st + off,         Ahi + aoff);                                    \
            cp16(st + 8192 + off,  Alo + aoff);                                    \
            cp16(st + 16384 + off, Bhi + boff);                                    \
            cp16(st + 24576 + off, Blo + boff);                                    \
        }                                                                          \
        {                                                                          \
            int row = ld_row1, ch = ld_ch1;                                        \
            uint32_t off = row * 64 + ((ch ^ ((row >> 1) & 3)) << 4);              \
            int gr = row0 + row; if (gr > M - 1) gr = M - 1;                       \
            size_t aoff = (size_t)gr * K + k0 + ch * 8;                            \
            size_t boff = (size_t)(col0 + row) * K + k0 + ch * 8;                  \
            cp16(st + off,         Ahi + aoff);                                    \
            cp16(st + 8192 + off,  Alo + aoff);                                    \
            cp16(st + 16384 + off, Bhi + boff);                                    \
            cp16(st + 24576 + off, Blo + boff);                                    \
        }                                                                          \
        asm volatile("cp.async.commit_group;\n");                                  \
    } while (0)

    LOAD_STAGE(0, 0);
    const int nk = K / 32;
    for (int kt = 0; kt < nk; kt++) {
        asm volatile("cp.async.wait_group 0;\n");
        __syncthreads();
        if (kt + 1 < nk) LOAD_STAGE((kt + 1) & 1, kt + 1);
        uint32_t st = sbase + (kt & 1) * 32768;

#pragma unroll
        for (int ks = 0; ks < 2; ks++) {
            uint32_t afh[4][4], afl[4][4], bf[4][2];
            int ar = lane & 15;
            int ach = ks * 2 + (lane >> 4);
            // A hi fragments (4 m16 tiles)
#pragma unroll
            for (int mt = 0; mt < 4; mt++) {
                int row = wm * 64 + mt * 16 + ar;
                uint32_t addr = st + row * 64 + ((ach ^ ((row >> 1) & 3)) << 4);
                ldsm4(addr, afh[mt][0], afh[mt][1], afh[mt][2], afh[mt][3]);
            }
            // B hi fragments (4 n8 tiles via 2 x ldmatrix.x4)
            int brr = (lane & 7) + ((lane & 16) ? 8 : 0);
            int bch = ks * 2 + ((lane >> 3) & 1);
#pragma unroll
            for (int nt2 = 0; nt2 < 2; nt2++) {
                int row = wn * 32 + nt2 * 16 + brr;
                uint32_t addr = st + 16384 + row * 64 + ((bch ^ ((row >> 1) & 3)) << 4);
                ldsm4(addr, bf[nt2 * 2][0], bf[nt2 * 2][1],
                      bf[nt2 * 2 + 1][0], bf[nt2 * 2 + 1][1]);
            }
            // hi x hi
#pragma unroll
            for (int mt = 0; mt < 4; mt++)
#pragma unroll
                for (int nt = 0; nt < 4; nt++)
                    mma16816(acc[mt][nt], afh[mt], bf[nt]);
            // A lo fragments
#pragma unroll
            for (int mt = 0; mt < 4; mt++) {
                int row = wm * 64 + mt * 16 + ar;
                uint32_t addr = st + 8192 + row * 64 + ((ach ^ ((row >> 1) & 3)) << 4);
                ldsm4(addr, afl[mt][0], afl[mt][1], afl[mt][2], afl[mt][3]);
            }
            // lo x hi
#pragma unroll
            for (int mt = 0; mt < 4; mt++)
#pragma unroll
                for (int nt = 0; nt < 4; nt++)
                    mma16816(acc[mt][nt], afl[mt], bf[nt]);
            // B lo fragments (reuse bf regs)
#pragma unroll
            for (int nt2 = 0; nt2 < 2; nt2++) {
                int row = wn * 32 + nt2 * 16 + brr;
                uint32_t addr = st + 24576 + row * 64 + ((bch ^ ((row >> 1) & 3)) << 4);
                ldsm4(addr, bf[nt2 * 2][0], bf[nt2 * 2][1],
                      bf[nt2 * 2 + 1][0], bf[nt2 * 2 + 1][1]);
            }
            // hi x lo
#pragma unroll
            for (int mt = 0; mt < 4; mt++)
#pragma unroll
                for (int nt = 0; nt < 4; nt++)
                    mma16816(acc[mt][nt], afh[mt], bf[nt]);
        }
        __syncthreads();
    }
#undef LOAD_STAGE

    // epilogue: bias add, float2 stores
#pragma unroll
    for (int mt = 0; mt < 4; mt++) {
        int gr0 = row0 + wm * 64 + mt * 16 + (lane >> 2);
#pragma unroll
        for (int nt = 0; nt < 4; nt++) {
            int gc = col0 + wn * 32 + nt * 8 + (lane & 3) * 2;
            float bb0 = bias[gc], bb1 = bias[gc + 1];
            if (gr0 < M) {
                float2 v; v.x = acc[mt][nt][0] + bb0; v.y = acc[mt][nt][1] + bb1;
                *(float2*)&C[(size_t)gr0 * N + gc] = v;
            }
            int gr1 = gr0 + 8;
            if (gr1 < M) {
                float2 v; v.x = acc[mt][nt][2] + bb0; v.y = acc[mt][nt][3] + bb1;
                *(float2*)&C[(size_t)gr1 * N + gc] = v;
            }
        }
    }
}

// ---------------------------------------------------------------------------
// Fused RMSNorm + RoPE
// ---------------------------------------------------------------------------
__global__ __launch_bounds__(256)
void norm_rope(float* __restrict__ q, float* __restrict__ k,
               const float* __restrict__ gq, const float* __restrict__ gk,
               const float* __restrict__ freqs,
               const int* __restrict__ p_h, const int* __restrict__ p_w,
               const int* __restrict__ p_sf)
{
    int l = blockIdx.x;
    int tid = threadIdx.x;
    __shared__ float sq[DIM], sk[DIM];
    __shared__ float redq[256], redk[256];

    size_t base = (size_t)l * DIM;
    float ssq = 0.f, ssk = 0.f;
    for (int i = tid; i < DIM; i += 256) {
        float a = q[base + i], b = k[base + i];
        sq[i] = a; sk[i] = b;
        ssq += a * a; ssk += b * b;
    }
    redq[tid] = ssq; redk[tid] = ssk;
    __syncthreads();
    for (int s = 128; s > 0; s >>= 1) {
        if (tid < s) { redq[tid] += redq[tid + s]; redk[tid] += redk[tid + s]; }
        __syncthreads();
    }
    float rq = rsqrtf(redq[0] * (1.f / DIM) + 1e-6f);
    float rk = rsqrtf(redk[0] * (1.f / DIM) + 1e-6f);

    int h = *p_h, w = *p_w, sf = *p_sf;
    int hw = h * w;
    int fr = l / hw, rem = l - fr * hw;
    int rr = rem / w, cc = rem - rr * w;
    const int c  = HD / 2;
    const int c1 = c / 3;
    const int c0 = c - 2 * c1;

    for (int p = tid; p < DIM / 2; p += 256) {
        int head = p >> 6;
        int i    = p & 63;
        int pos  = (i < c0) ? (sf + fr) : ((i < c0 + c1) ? rr : cc);
        float ang = freqs[pos * c + i];
        float cs = cosf(ang), sn = sinf(ang);
        int idx = head * HD + 2 * i;

        float qre = sq[idx] * rq * gq[idx];
        float qim = sq[idx + 1] * rq * gq[idx + 1];
        q[base + idx]     = qre * cs - qim * sn;
        q[base + idx + 1] = qre * sn + qim * cs;

        float kre = sk[idx] * rk * gk[idx];
        float kim = sk[idx + 1] * rk * gk[idx + 1];
        k[base + idx]     = kre * cs - kim * sn;
        k[base + idx + 1] = kre * sn + kim * cs;
    }
}

// ---------------------------------------------------------------------------
// Flash attention, fp32 SIMT
// ---------------------------------------------------------------------------
__global__ __launch_bounds__(128)
void attn(const float* __restrict__ q, const float* __restrict__ k,
          const float* __restrict__ v, float* __restrict__ o,
          const int* __restrict__ p_h, const int* __restrict__ p_w,
          const int* __restrict__ p_local, const int* __restrict__ p_sink)
{
    const int BQ = 64, BKV = 32;
    int qb = blockIdx.x, hd = blockIdx.y;
    int tid = threadIdx.x;
    int qrow = tid >> 1, hf = tid & 1;
    int lq = qb * BQ + qrow;
    bool active = lq < LSEQ;
    int lql = active ? lq : (LSEQ - 1);

    int hw = (*p_h) * (*p_w);
    int local = *p_local, sink = *p_sink;
    int fi = lql / hw;

    float qreg[64];
    const float scl = rsqrtf((float)HD);
    {
        const float* qp = q + (size_t)lql * DIM + hd * HD + hf * 64;
#pragma unroll
        for (int i = 0; i < 64; i++) qreg[i] = qp[i] * scl;
    }

    float m = -1e30f, lsum = 0.f;
    float acc[64];
#pragma unroll
    for (int i = 0; i < 64; i++) acc[i] = 0.f;

    __shared__ float Ks[BKV][HD];
    __shared__ float Vs[BKV][HD];

    int last_q = min(qb * BQ + BQ - 1, LSEQ - 1);
    int kend = (last_q / hw + 1) * hw;

    for (int kb = 0; kb < kend; kb += BKV) {
        __syncthreads();
        for (int idx = tid; idx < BKV * HD; idx += 128) {
            int r = idx >> 7, cidx = idx & 127;
            int lk = kb + r;
            if (lk < LSEQ) {
                size_t off = (size_t)lk * DIM + hd * HD + cidx;
                Ks[r][cidx] = k[off];
                Vs[r][cidx] = v[off];
            } else {
                Ks[r][cidx] = 0.f; Vs[r][cidx] = 0.f;
            }
        }
        __syncthreads();

        float s[BKV];
#pragma unroll
        for (int j = 0; j < BKV; j++) {
            const float4* kr = (const float4*)&Ks[j][hf * 64];
            float s0 = 0.f, s1 = 0.f, s2 = 0.f, s3 = 0.f;
#pragma unroll
            for (int i4 = 0; i4 < 16; i4++) {
                float4 kv = kr[i4];
                s0 += qreg[i4 * 4 + 0] * kv.x;
                s1 += qreg[i4 * 4 + 1] * kv.y;
                s2 += qreg[i4 * 4 + 2] * kv.z;
                s3 += qreg[i4 * 4 + 3] * kv.w;
            }
            s[j] = (s0 + s1) + (s2 + s3);
        }
#pragma unroll
        for (int j = 0; j < BKV; j++)
            s[j] += __shfl_xor_sync(0xffffffffu, s[j], 1);

        float tmax = -1e30f;
#pragma unroll
        for (int j = 0; j < BKV; j++) {
            int lk = kb + j;
            int fj = lk / hw;
            bool ok = active && (lk < LSEQ) && (fj <= fi) &&
                      (((fi - fj) < local) || (fj < sink));
            s[j] = ok ? s[j] : -1e30f;
            tmax = fmaxf(tmax, s[j]);
        }
        if (tmax > -1e29f) {
            float mnew = fmaxf(m, tmax);
            float corr = __expf(m - mnew);
            lsum *= corr;
#pragma unroll
            for (int i = 0; i < 64; i++) acc[i] *= corr;
#pragma unroll
            for (int j = 0; j < BKV; j++) {
                float pj = __expf(s[j] - mnew);
                lsum += pj;
                s[j] = pj;
            }
#pragma unroll
            for (int j = 0; j < BKV; j++) {
                float pj = s[j];
                const float4* vr = (const float4*)&Vs[j][hf * 64];
#pragma unroll
                for (int i4 = 0; i4 < 16; i4++) {
                    float4 vv = vr[i4];
                    acc[i4 * 4 + 0] += pj * vv.x;
                    acc[i4 * 4 + 1] += pj * vv.y;
                    acc[i4 * 4 + 2] += pj * vv.z;
                    acc[i4 * 4 + 3] += pj * vv.w;
                }
            }
            m = mnew;
        }
    }

    if (active) {
        float inv = 1.f / lsum;
        float* op = o + (size_t)lq * DIM + hd * HD + hf * 64;
#pragma unroll
        for (int i = 0; i < 64; i++) op[i] = acc[i] * inv;
    }
}

// ---------------------------------------------------------------------------
extern "C" void kernel_launch(void* const* d_in, const int* in_sizes, int n_in,
                              void* d_out, int out_size)
{
    const float* x     = (const float*)d_in[0];
    const float* freqs = (const float*)d_in[1];
    const float* Wq    = (const float*)d_in[2];
    const float* bq    = (const float*)d_in[3];
    const float* Wk    = (const float*)d_in[4];
    const float* bk    = (const float*)d_in[5];
    const float* Wv    = (const float*)d_in[6];
    const float* bv    = (const float*)d_in[7];
    const float* Wo    = (const float*)d_in[8];
    const float* bo    = (const float*)d_in[9];
    const float* gq    = (const float*)d_in[10];
    const float* gk    = (const float*)d_in[11];
    const int* p_h     = (const int*)d_in[13];
    const int* p_w     = (const int*)d_in[14];
    const int* p_local = (const int*)d_in[16];
    const int* p_sink  = (const int*)d_in[17];
    const int* p_sf    = (const int*)d_in[18];
    float* out = (float*)d_out;
    (void)in_sizes; (void)n_in; (void)out_size;

    float *pq, *pk, *pv, *po;
    cudaGetSymbolAddress((void**)&pq, g_q);
    cudaGetSymbolAddress((void**)&pk, g_k);
    cudaGetSymbolAddress((void**)&pv, g_v);
    cudaGetSymbolAddress((void**)&po, g_o);

    __half *xhi, *xlo, *ohi, *olo;
    __half *wqhi, *wqlo, *wkhi, *wklo, *wvhi, *wvlo, *wohi, *wolo;
    cudaGetSymbolAddress((void**)&xhi, g_xhi);
    cudaGetSymbolAddress((void**)&xlo, g_xlo);
    cudaGetSymbolAddress((void**)&ohi, g_ohi);
    cudaGetSymbolAddress((void**)&olo, g_olo);
    cudaGetSymbolAddress((void**)&wqhi, g_wqhi);
    cudaGetSymbolAddress((void**)&wqlo, g_wqlo);
    cudaGetSymbolAddress((void**)&wkhi, g_wkhi);
    cudaGetSymbolAddress((void**)&wklo, g_wklo);
    cudaGetSymbolAddress((void**)&wvhi, g_wvhi);
    cudaGetSymbolAddress((void**)&wvlo, g_wvlo);
    cudaGetSymbolAddress((void**)&wohi, g_wohi);
    cudaGetSymbolAddress((void**)&wolo, g_wolo);

    cudaFuncSetAttribute(gemm_mma, cudaFuncAttributeMaxDynamicSharedMemorySize, 65536);

    const int nx = LSEQ * DIM, nw = DIM * DIM;
    split_kern<<<(nx + 255) / 256, 256>>>(x, xhi, xlo, nx);
    split_kern<<<(nw + 255) / 256, 256>>>(Wq, wqhi, wqlo, nw);
    split_kern<<<(nw + 255) / 256, 256>>>(Wk, wkhi, wklo, nw);
    split_kern<<<(nw + 255) / 256, 256>>>(Wv, wvhi, wvlo, nw);
    split_kern<<<(nw + 255) / 256, 256>>>(Wo, wohi, wolo, nw);

    dim3 gg(DIM / 128, (LSEQ + 127) / 128);
    gemm_mma<<<gg, 256, 65536>>>(xhi, xlo, wqhi, wqlo, bq, pq, LSEQ);
    gemm_mma<<<gg, 256, 65536>>>(xhi, xlo, wkhi, wklo, bk, pk, LSEQ);
    gemm_mma<<<gg, 256, 65536>>>(xhi, xlo, wvhi, wvlo, bv, pv, LSEQ);

    norm_rope<<<LSEQ, 256>>>(pq, pk, gq, gk, freqs, p_h, p_w, p_sf);
    attn<<<dim3((LSEQ + 63) / 64, NH), 128>>>(pq, pk, pv, po, p_h, p_w, p_local, p_sink);

    split_kern<<<(nx + 255) / 256, 256>>>(po, ohi, olo, nx);
    gemm_mma<<<gg, 256, 65536>>>(ohi, olo, wohi, wolo, bo, out, LSEQ);
}

// round 7
// speedup vs baseline: 4.2449x; 3.4289x over previous
#include <cuda_runtime.h>
#include <cuda_fp16.h>
#include <cstdint>
#include <math.h>

#define LSEQ 4680
#define DIM  1536
#define NH   12
#define HD   128

// fp32 scratch
__device__ float g_q[LSEQ * DIM];
__device__ float g_k[LSEQ * DIM];
__device__ float g_v[LSEQ * DIM];
__device__ float g_o[LSEQ * DIM];

// split fp16 operands (16B alignment for cp.async)
__device__ __align__(256) __half g_xhi[LSEQ * DIM];
__device__ __align__(256) __half g_xlo[LSEQ * DIM];
__device__ __align__(256) __half g_ohi[LSEQ * DIM];
__device__ __align__(256) __half g_olo[LSEQ * DIM];
__device__ __align__(256) __half g_wqhi[DIM * DIM];
__device__ __align__(256) __half g_wqlo[DIM * DIM];
__device__ __align__(256) __half g_wkhi[DIM * DIM];
__device__ __align__(256) __half g_wklo[DIM * DIM];
__device__ __align__(256) __half g_wvhi[DIM * DIM];
__device__ __align__(256) __half g_wvlo[DIM * DIM];
__device__ __align__(256) __half g_wohi[DIM * DIM];
__device__ __align__(256) __half g_wolo[DIM * DIM];

// attention split operands
__device__ __align__(256) __half g_qhi[LSEQ * DIM];
__device__ __align__(256) __half g_qlo[LSEQ * DIM];
__device__ __align__(256) __half g_khi[LSEQ * DIM];
__device__ __align__(256) __half g_klo[LSEQ * DIM];
// V transposed: [dim 1536][seq 4680], +64 pad for tile-overrun reads
__device__ __align__(256) __half g_vthi[DIM * LSEQ + 64];
__device__ __align__(256) __half g_vtlo[DIM * LSEQ + 64];

// ---------------------------------------------------------------------------
__global__ __launch_bounds__(256)
void split_kern(const float* __restrict__ in, __half* __restrict__ hi,
                __half* __restrict__ lo, int n)
{
    int i = blockIdx.x * 256 + threadIdx.x;
    if (i < n) {
        float a = in[i];
        __half h = __float2half_rn(a);
        hi[i] = h;
        lo[i] = __float2half_rn(a - __half2float(h));
    }
}

// ---------------------------------------------------------------------------
// mma helpers
// ---------------------------------------------------------------------------
__device__ __forceinline__ void ldsm4(uint32_t a, uint32_t& r0, uint32_t& r1,
                                      uint32_t& r2, uint32_t& r3)
{
    asm volatile("ldmatrix.sync.aligned.m8n8.x4.shared.b16 {%0,%1,%2,%3},[%4];\n"
                 : "=r"(r0), "=r"(r1), "=r"(r2), "=r"(r3) : "r"(a));
}
__device__ __forceinline__ void mma16816(float* c, const uint32_t* a, const uint32_t* b)
{
    asm volatile("mma.sync.aligned.m16n8k16.row.col.f32.f16.f16.f32 "
                 "{%0,%1,%2,%3},{%4,%5,%6,%7},{%8,%9},{%0,%1,%2,%3};\n"
                 : "+f"(c[0]), "+f"(c[1]), "+f"(c[2]), "+f"(c[3])
                 : "r"(a[0]), "r"(a[1]), "r"(a[2]), "r"(a[3]), "r"(b[0]), "r"(b[1]));
}
__device__ __forceinline__ void cp16(uint32_t dst, const void* src)
{
    asm volatile("cp.async.cg.shared.global [%0],[%1],16;\n" :: "r"(dst), "l"(src));
}
__device__ __forceinline__ uint32_t f2h2(float a, float b)
{
    __half2 h = __floats2half2_rn(a, b);
    return *(uint32_t*)&h;
}

// ---------------------------------------------------------------------------
// GEMM (unchanged from round 5): C = A @ B^T + bias, split-fp16 3-term.
// ---------------------------------------------------------------------------
__global__ __launch_bounds__(256, 2)
void gemm_mma(const __half* __restrict__ Ahi, const __half* __restrict__ Alo,
              const __half* __restrict__ Bhi, const __half* __restrict__ Blo,
              const float* __restrict__ bias, float* __restrict__ C, int M)
{
    const int N = DIM, K = DIM;
    extern __shared__ char smbuf[];
    uint32_t sbase = (uint32_t)__cvta_generic_to_shared(smbuf);
    int tid = threadIdx.x;
    int lane = tid & 31, warp = tid >> 5;
    int wm = warp & 1, wn = warp >> 1;
    int row0 = blockIdx.y * 128, col0 = blockIdx.x * 128;

    float acc[4][4][4];
#pragma unroll
    for (int mt = 0; mt < 4; mt++)
#pragma unroll
        for (int nt = 0; nt < 4; nt++)
#pragma unroll
            for (int i = 0; i < 4; i++) acc[mt][nt][i] = 0.f;

    int ld_row0 = tid >> 2, ld_ch0 = tid & 3;
    int ld_row1 = (tid + 256) >> 2, ld_ch1 = tid & 3;

#define LOAD_STAGE(s, kt)                                                          \
    do {                                                                           \
        int k0 = (kt) * 32;                                                        \
        uint32_t st = sbase + (s) * 32768;                                         \
        {                                                                          \
            int row = ld_row0, ch = ld_ch0;                                        \
            uint32_t off = row * 64 + ((ch ^ ((row >> 1) & 3)) << 4);              \
            int gr = row0 + row; if (gr > M - 1) gr = M - 1;                       \
            size_t aoff = (size_t)gr * K + k0 + ch * 8;                            \
            size_t boff = (size_t)(col0 + row) * K + k0 + ch * 8;                  \
            cp16(st + off,         Ahi + aoff);                                    \
            cp16(st + 8192 + off,  Alo + aoff);                                    \
            cp16(st + 16384 + off, Bhi + boff);                                    \
            cp16(st + 24576 + off, Blo + boff);                                    \
        }                                                                          \
        {                                                                          \
            int row = ld_row1, ch = ld_ch1;                                        \
            uint32_t off = row * 64 + ((ch ^ ((row >> 1) & 3)) << 4);              \
            int gr = row0 + row; if (gr > M - 1) gr = M - 1;                       \
            size_t aoff = (size_t)gr * K + k0 + ch * 8;                            \
            size_t boff = (size_t)(col0 + row) * K + k0 + ch * 8;                  \
            cp16(st + off,         Ahi + aoff);                                    \
            cp16(st + 8192 + off,  Alo + aoff);                                    \
            cp16(st + 16384 + off, Bhi + boff);                                    \
            cp16(st + 24576 + off, Blo + boff);                                    \
        }                                                                          \
        asm volatile("cp.async.commit_group;\n");                                  \
    } while (0)

    LOAD_STAGE(0, 0);
    const int nk = K / 32;
    for (int kt = 0; kt < nk; kt++) {
        asm volatile("cp.async.wait_group 0;\n");
        __syncthreads();
        if (kt + 1 < nk) LOAD_STAGE((kt + 1) & 1, kt + 1);
        uint32_t st = sbase + (kt & 1) * 32768;

#pragma unroll
        for (int ks = 0; ks < 2; ks++) {
            uint32_t afh[4][4], afl[4][4], bf[4][2];
            int ar = lane & 15;
            int ach = ks * 2 + (lane >> 4);
#pragma unroll
            for (int mt = 0; mt < 4; mt++) {
                int row = wm * 64 + mt * 16 + ar;
                uint32_t addr = st + row * 64 + ((ach ^ ((row >> 1) & 3)) << 4);
                ldsm4(addr, afh[mt][0], afh[mt][1], afh[mt][2], afh[mt][3]);
            }
            int brr = (lane & 7) + ((lane & 16) ? 8 : 0);
            int bch = ks * 2 + ((lane >> 3) & 1);
#pragma unroll
            for (int nt2 = 0; nt2 < 2; nt2++) {
                int row = wn * 32 + nt2 * 16 + brr;
                uint32_t addr = st + 16384 + row * 64 + ((bch ^ ((row >> 1) & 3)) << 4);
                ldsm4(addr, bf[nt2 * 2][0], bf[nt2 * 2][1],
                      bf[nt2 * 2 + 1][0], bf[nt2 * 2 + 1][1]);
            }
#pragma unroll
            for (int mt = 0; mt < 4; mt++)
#pragma unroll
                for (int nt = 0; nt < 4; nt++)
                    mma16816(acc[mt][nt], afh[mt], bf[nt]);
#pragma unroll
            for (int mt = 0; mt < 4; mt++) {
                int row = wm * 64 + mt * 16 + ar;
                uint32_t addr = st + 8192 + row * 64 + ((ach ^ ((row >> 1) & 3)) << 4);
                ldsm4(addr, afl[mt][0], afl[mt][1], afl[mt][2], afl[mt][3]);
            }
#pragma unroll
            for (int mt = 0; mt < 4; mt++)
#pragma unroll
                for (int nt = 0; nt < 4; nt++)
                    mma16816(acc[mt][nt], afl[mt], bf[nt]);
#pragma unroll
            for (int nt2 = 0; nt2 < 2; nt2++) {
                int row = wn * 32 + nt2 * 16 + brr;
                uint32_t addr = st + 24576 + row * 64 + ((bch ^ ((row >> 1) & 3)) << 4);
                ldsm4(addr, bf[nt2 * 2][0], bf[nt2 * 2][1],
                      bf[nt2 * 2 + 1][0], bf[nt2 * 2 + 1][1]);
            }
#pragma unroll
            for (int mt = 0; mt < 4; mt++)
#pragma unroll
                for (int nt = 0; nt < 4; nt++)
                    mma16816(acc[mt][nt], afh[mt], bf[nt]);
        }
        __syncthreads();
    }
#undef LOAD_STAGE

#pragma unroll
    for (int mt = 0; mt < 4; mt++) {
        int gr0 = row0 + wm * 64 + mt * 16 + (lane >> 2);
#pragma unroll
        for (int nt = 0; nt < 4; nt++) {
            int gc = col0 + wn * 32 + nt * 8 + (lane & 3) * 2;
            float bb0 = bias[gc], bb1 = bias[gc + 1];
            if (gr0 < M) {
                float2 v; v.x = acc[mt][nt][0] + bb0; v.y = acc[mt][nt][1] + bb1;
                *(float2*)&C[(size_t)gr0 * N + gc] = v;
            }
            int gr1 = gr0 + 8;
            if (gr1 < M) {
                float2 v; v.x = acc[mt][nt][2] + bb0; v.y = acc[mt][nt][3] + bb1;
                *(float2*)&C[(size_t)gr1 * N + gc] = v;
            }
        }
    }
}

// ---------------------------------------------------------------------------
// Fused RMSNorm + RoPE -> writes split-fp16 Q (scaled by 1/sqrt(d)) and K.
// ---------------------------------------------------------------------------
__global__ __launch_bounds__(256)
void norm_rope(const float* __restrict__ q, const float* __restrict__ k,
               __half* __restrict__ qhi, __half* __restrict__ qlo,
               __half* __restrict__ khi, __half* __restrict__ klo,
               const float* __restrict__ gq, const float* __restrict__ gk,
               const float* __restrict__ freqs,
               const int* __restrict__ p_h, const int* __restrict__ p_w,
               const int* __restrict__ p_sf)
{
    int l = blockIdx.x;
    int tid = threadIdx.x;
    __shared__ float sq[DIM], sk[DIM];
    __shared__ float redq[256], redk[256];

    size_t base = (size_t)l * DIM;
    float ssq = 0.f, ssk = 0.f;
    for (int i = tid; i < DIM; i += 256) {
        float a = q[base + i], b = k[base + i];
        sq[i] = a; sk[i] = b;
        ssq += a * a; ssk += b * b;
    }
    redq[tid] = ssq; redk[tid] = ssk;
    __syncthreads();
    for (int s = 128; s > 0; s >>= 1) {
        if (tid < s) { redq[tid] += redq[tid + s]; redk[tid] += redk[tid + s]; }
        __syncthreads();
    }
    float rq = rsqrtf(redq[0] * (1.f / DIM) + 1e-6f);
    float rk = rsqrtf(redk[0] * (1.f / DIM) + 1e-6f);

    int h = *p_h, w = *p_w, sf = *p_sf;
    int hw = h * w;
    int fr = l / hw, rem = l - fr * hw;
    int rr = rem / w, cc = rem - rr * w;
    const int c  = HD / 2;
    const int c1 = c / 3;
    const int c0 = c - 2 * c1;
    const float scl = rsqrtf((float)HD);

    for (int p = tid; p < DIM / 2; p += 256) {
        int head = p >> 6;
        int i    = p & 63;
        int pos  = (i < c0) ? (sf + fr) : ((i < c0 + c1) ? rr : cc);
        float ang = freqs[pos * c + i];
        float cs = cosf(ang), sn = sinf(ang);
        int idx = head * HD + 2 * i;

        float qre = sq[idx] * rq * gq[idx];
        float qim = sq[idx + 1] * rq * gq[idx + 1];
        float q0 = (qre * cs - qim * sn) * scl;
        float q1 = (qre * sn + qim * cs) * scl;
        __half h0 = __float2half_rn(q0), h1 = __float2half_rn(q1);
        qhi[base + idx] = h0; qlo[base + idx] = __float2half_rn(q0 - __half2float(h0));
        qhi[base + idx + 1] = h1; qlo[base + idx + 1] = __float2half_rn(q1 - __half2float(h1));

        float kre = sk[idx] * rk * gk[idx];
        float kim = sk[idx + 1] * rk * gk[idx + 1];
        float k0 = kre * cs - kim * sn;
        float k1 = kre * sn + kim * cs;
        __half g0 = __float2half_rn(k0), g1 = __float2half_rn(k1);
        khi[base + idx] = g0; klo[base + idx] = __float2half_rn(k0 - __half2float(g0));
        khi[base + idx + 1] = g1; klo[base + idx + 1] = __float2half_rn(k1 - __half2float(g1));
    }
}

// ---------------------------------------------------------------------------
// V transpose + split: v[seq][dim] fp32 -> vt{hi,lo}[dim][seq] fp16
// ---------------------------------------------------------------------------
__global__ __launch_bounds__(256)
void prep_vt(const float* __restrict__ v, __half* __restrict__ vthi,
             __half* __restrict__ vtlo)
{
    __shared__ float t[32][33];
    int c0 = blockIdx.y * 32;
    int s0 = blockIdx.x * 32;
    int x = threadIdx.x & 31, y = threadIdx.x >> 5;   // 32 x 8
#pragma unroll
    for (int i = y; i < 32; i += 8) {
        int s = s0 + i;
        t[i][x] = (s < LSEQ) ? v[(size_t)s * DIM + c0 + x] : 0.f;
    }
    __syncthreads();
#pragma unroll
    for (int i = y; i < 32; i += 8) {
        int d = c0 + i;
        int s = s0 + x;
        if (s < LSEQ) {
            float a = t[x][i];
            __half h = __float2half_rn(a);
            vthi[(size_t)d * LSEQ + s] = h;
            vtlo[(size_t)d * LSEQ + s] = __float2half_rn(a - __half2float(h));
        }
    }
}

// ---------------------------------------------------------------------------
// Tensor-core flash attention.
// Block: 64 queries x 1 head, 4 warps (16 q-rows each), 64-key tiles.
// QK: 3-term split fp16 mma. PV: P fp16 x (Vhi + Vlo).
// smem 64KB: Khi[64][128d], Klo, Vthi[128d][64k], Vtlo  (16KB each), swizzled.
// ---------------------------------------------------------------------------
__global__ __launch_bounds__(128, 2)
void attn_mma(const __half* __restrict__ qhi, const __half* __restrict__ qlo,
              const __half* __restrict__ khi, const __half* __restrict__ klo,
              const __half* __restrict__ vthi, const __half* __restrict__ vtlo,
              float* __restrict__ o,
              const int* __restrict__ p_h, const int* __restrict__ p_w,
              const int* __restrict__ p_local, const int* __restrict__ p_sink)
{
    extern __shared__ char smema[];
    uint32_t sb = (uint32_t)__cvta_generic_to_shared(smema);
    const uint32_t KHI = sb, VHI = sb + 32768;     // lo partner at +16384
    int tid = threadIdx.x, lane = tid & 31, warp = tid >> 5;
    int qb = blockIdx.x, head = blockIdx.y;
    int r = lane >> 2, cg = lane & 3;

    int hw = (*p_h) * (*p_w);
    int local = *p_local, sink = *p_sink;

    int q0 = qb * 64 + warp * 16;
    int qrow0 = q0 + r, qrow1 = q0 + r + 8;
    int qc0 = min(qrow0, LSEQ - 1), qc1 = min(qrow1, LSEQ - 1);
    int fi0 = qrow0 / hw, fi1 = qrow1 / hw;

    // Q fragments via direct global half2 loads (once per block)
    uint32_t qh[8][4], ql[8][4];
    {
        int cb = head * HD + cg * 2;
#pragma unroll
        for (int dc = 0; dc < 8; dc++) {
            int cc = cb + dc * 16;
            qh[dc][0] = *(const uint32_t*)&qhi[(size_t)qc0 * DIM + cc];
            qh[dc][1] = *(const uint32_t*)&qhi[(size_t)qc1 * DIM + cc];
            qh[dc][2] = *(const uint32_t*)&qhi[(size_t)qc0 * DIM + cc + 8];
            qh[dc][3] = *(const uint32_t*)&qhi[(size_t)qc1 * DIM + cc + 8];
            ql[dc][0] = *(const uint32_t*)&qlo[(size_t)qc0 * DIM + cc];
            ql[dc][1] = *(const uint32_t*)&qlo[(size_t)qc1 * DIM + cc];
            ql[dc][2] = *(const uint32_t*)&qlo[(size_t)qc0 * DIM + cc + 8];
            ql[dc][3] = *(const uint32_t*)&qlo[(size_t)qc1 * DIM + cc + 8];
        }
    }

    float m0 = -1e30f, m1 = -1e30f, l0 = 0.f, l1 = 0.f;
    float oacc[16][4];
#pragma unroll
    for (int nt = 0; nt < 16; nt++)
#pragma unroll
        for (int i = 0; i < 4; i++) oacc[nt][i] = 0.f;

    // loader coords
    int krow = tid >> 1;              // 0..63 (key row)
    int kc0  = (tid & 1) * 8;         // chunk base within 16
    int vrow = tid;                   // 0..127 (dim row)

    int qlast = min(qb * 64 + 63, LSEQ - 1);
    int kend = (qlast / hw + 1) * hw;
    int ntiles = (kend + 63) / 64;

    int g = lane >> 3, lr = lane & 7;

    for (int kt = 0; kt < ntiles; kt++) {
        int kb = kt * 64;
        // ---- load K (64 x 128 dims) and Vt (128 dims x 64 keys), hi+lo ----
        {
            int krg = min(kb + krow, LSEQ - 1);
            size_t kgb = (size_t)krg * DIM + head * HD;
#pragma unroll
            for (int j = 0; j < 8; j++) {
                int ch = kc0 + j;
                uint32_t off = krow * 256 + ((ch ^ (krow & 7)) << 4);
                cp16(KHI + off,          khi + kgb + ch * 8);
                cp16(KHI + 16384 + off,  klo + kgb + ch * 8);
            }
            size_t vgb = (size_t)(head * HD + vrow) * LSEQ + kb;
#pragma unroll
            for (int ch = 0; ch < 8; ch++) {
                uint32_t off = vrow * 128 + ((ch ^ (vrow & 7)) << 4);
                cp16(VHI + off,          vthi + vgb + ch * 8);
                cp16(VHI + 16384 + off,  vtlo + vgb + ch * 8);
            }
        }
        asm volatile("cp.async.commit_group;\n");
        asm volatile("cp.async.wait_group 0;\n");
        __syncthreads();

        // ---- QK^T: scores for 8 n-tiles (64 keys) ----
        float s[8][4];
#pragma unroll
        for (int nt = 0; nt < 8; nt++)
#pragma unroll
            for (int i = 0; i < 4; i++) s[nt][i] = 0.f;

#pragma unroll
        for (int dc = 0; dc < 8; dc++) {
            int ch = 2 * dc + (g & 1);
#pragma unroll
            for (int np = 0; np < 4; np++) {
                int row = np * 16 + ((g >> 1) << 3) + lr;
                uint32_t addr = KHI + row * 256 + ((ch ^ (row & 7)) << 4);
                uint32_t bh0[2], bh1[2], bl0[2], bl1[2];
                ldsm4(addr, bh0[0], bh0[1], bh1[0], bh1[1]);
                ldsm4(addr + 16384, bl0[0], bl0[1], bl1[0], bl1[1]);
                mma16816(s[np * 2],     qh[dc], bh0);
                mma16816(s[np * 2 + 1], qh[dc], bh1);
                mma16816(s[np * 2],     ql[dc], bh0);
                mma16816(s[np * 2 + 1], ql[dc], bh1);
                mma16816(s[np * 2],     qh[dc], bl0);
                mma16816(s[np * 2 + 1], qh[dc], bl1);
            }
        }

        // ---- mask + online softmax ----
        float tm0 = -1e30f, tm1 = -1e30f;
#pragma unroll
        for (int nt = 0; nt < 8; nt++) {
            int n0 = kb + nt * 8 + cg * 2;
            int fj0 = n0 / hw, fj1 = (n0 + 1) / hw;
            bool okA0 = (fj0 <= fi0) && (((fi0 - fj0) < local) || (fj0 < sink));
            bool okB0 = (fj1 <= fi0) && (((fi0 - fj1) < local) || (fj1 < sink));
            bool okA1 = (fj0 <= fi1) && (((fi1 - fj0) < local) || (fj0 < sink));
            bool okB1 = (fj1 <= fi1) && (((fi1 - fj1) < local) || (fj1 < sink));
            s[nt][0] = okA0 ? s[nt][0] : -1e30f;
            s[nt][1] = okB0 ? s[nt][1] : -1e30f;
            s[nt][2] = okA1 ? s[nt][2] : -1e30f;
            s[nt][3] = okB1 ? s[nt][3] : -1e30f;
            tm0 = fmaxf(tm0, fmaxf(s[nt][0], s[nt][1]));
            tm1 = fmaxf(tm1, fmaxf(s[nt][2], s[nt][3]));
        }
        tm0 = fmaxf(tm0, __shfl_xor_sync(0xffffffffu, tm0, 1));
        tm0 = fmaxf(tm0, __shfl_xor_sync(0xffffffffu, tm0, 2));
        tm1 = fmaxf(tm1, __shfl_xor_sync(0xffffffffu, tm1, 1));
        tm1 = fmaxf(tm1, __shfl_xor_sync(0xffffffffu, tm1, 2));

        float mn0 = fmaxf(m0, tm0), mn1 = fmaxf(m1, tm1);
        float cr0 = __expf(m0 - mn0), cr1 = __expf(m1 - mn1);
        m0 = mn0; m1 = mn1;
        l0 *= cr0; l1 *= cr1;
#pragma unroll
        for (int nt = 0; nt < 16; nt++) {
            oacc[nt][0] *= cr0; oacc[nt][1] *= cr0;
            oacc[nt][2] *= cr1; oacc[nt][3] *= cr1;
        }
        float ps0 = 0.f, ps1 = 0.f;
#pragma unroll
        for (int nt = 0; nt < 8; nt++) {
            float p0 = __expf(s[nt][0] - mn0);
            float p1 = __expf(s[nt][1] - mn0);
            float p2 = __expf(s[nt][2] - mn1);
            float p3 = __expf(s[nt][3] - mn1);
            ps0 += p0 + p1; ps1 += p2 + p3;
            s[nt][0] = p0; s[nt][1] = p1; s[nt][2] = p2; s[nt][3] = p3;
        }
        l0 += ps0; l1 += ps1;

        // pack P into A-fragments (4 k-chunks of 16 keys)
        uint32_t pa[4][4];
#pragma unroll
        for (int kp = 0; kp < 4; kp++) {
            pa[kp][0] = f2h2(s[2 * kp][0],     s[2 * kp][1]);
            pa[kp][1] = f2h2(s[2 * kp][2],     s[2 * kp][3]);
            pa[kp][2] = f2h2(s[2 * kp + 1][0], s[2 * kp + 1][1]);
            pa[kp][3] = f2h2(s[2 * kp + 1][2], s[2 * kp + 1][3]);
        }

        // ---- P @ V ----
#pragma unroll
        for (int kp = 0; kp < 4; kp++) {
            int ch = 2 * kp + (g & 1);
#pragma unroll
            for (int dp = 0; dp < 8; dp++) {
                int row = dp * 16 + ((g >> 1) << 3) + lr;
                uint32_t addr = VHI + row * 128 + ((ch ^ (row & 7)) << 4);
                uint32_t bh0[2], bh1[2], bl0[2], bl1[2];
                ldsm4(addr, bh0[0], bh0[1], bh1[0], bh1[1]);
                ldsm4(addr + 16384, bl0[0], bl0[1], bl1[0], bl1[1]);
                mma16816(oacc[dp * 2],     pa[kp], bh0);
                mma16816(oacc[dp * 2 + 1], pa[kp], bh1);
                mma16816(oacc[dp * 2],     pa[kp], bl0);
                mma16816(oacc[dp * 2 + 1], pa[kp], bl1);
            }
        }
        __syncthreads();
    }

    // ---- epilogue ----
    l0 += __shfl_xor_sync(0xffffffffu, l0, 1);
    l0 += __shfl_xor_sync(0xffffffffu, l0, 2);
    l1 += __shfl_xor_sync(0xffffffffu, l1, 1);
    l1 += __shfl_xor_sync(0xffffffffu, l1, 2);
    float inv0 = 1.f / l0, inv1 = 1.f / l1;
#pragma unroll
    for (int nt = 0; nt < 16; nt++) {
        int col = head * HD + nt * 8 + cg * 2;
        if (qrow0 < LSEQ) {
            float2 v; v.x = oacc[nt][0] * inv0; v.y = oacc[nt][1] * inv0;
            *(float2*)&o[(size_t)qrow0 * DIM + col] = v;
        }
        if (qrow1 < LSEQ) {
            float2 v; v.x = oacc[nt][2] * inv1; v.y = oacc[nt][3] * inv1;
            *(float2*)&o[(size_t)qrow1 * DIM + col] = v;
        }
    }
}

// ---------------------------------------------------------------------------
extern "C" void kernel_launch(void* const* d_in, const int* in_sizes, int n_in,
                              void* d_out, int out_size)
{
    const float* x     = (const float*)d_in[0];
    const float* freqs = (const float*)d_in[1];
    const float* Wq    = (const float*)d_in[2];
    const float* bq    = (const float*)d_in[3];
    const float* Wk    = (const float*)d_in[4];
    const float* bk    = (const float*)d_in[5];
    const float* Wv    = (const float*)d_in[6];
    const float* bv    = (const float*)d_in[7];
    const float* Wo    = (const float*)d_in[8];
    const float* bo    = (const float*)d_in[9];
    const float* gq    = (const float*)d_in[10];
    const float* gk    = (const float*)d_in[11];
    const int* p_h     = (const int*)d_in[13];
    const int* p_w     = (const int*)d_in[14];
    const int* p_local = (const int*)d_in[16];
    const int* p_sink  = (const int*)d_in[17];
    const int* p_sf    = (const int*)d_in[18];
    float* out = (float*)d_out;
    (void)in_sizes; (void)n_in; (void)out_size;

    float *pq, *pk, *pv, *po;
    cudaGetSymbolAddress((void**)&pq, g_q);
    cudaGetSymbolAddress((void**)&pk, g_k);
    cudaGetSymbolAddress((void**)&pv, g_v);
    cudaGetSymbolAddress((void**)&po, g_o);

    __half *xhi, *xlo, *ohi, *olo;
    __half *wqhi, *wqlo, *wkhi, *wklo, *wvhi, *wvlo, *wohi, *wolo;
    __half *aqhi, *aqlo, *akhi, *aklo, *vthi, *vtlo;
    cudaGetSymbolAddress((void**)&xhi, g_xhi);
    cudaGetSymbolAddress((void**)&xlo, g_xlo);
    cudaGetSymbolAddress((void**)&ohi, g_ohi);
    cudaGetSymbolAddress((void**)&olo, g_olo);
    cudaGetSymbolAddress((void**)&wqhi, g_wqhi);
    cudaGetSymbolAddress((void**)&wqlo, g_wqlo);
    cudaGetSymbolAddress((void**)&wkhi, g_wkhi);
    cudaGetSymbolAddress((void**)&wklo, g_wklo);
    cudaGetSymbolAddress((void**)&wvhi, g_wvhi);
    cudaGetSymbolAddress((void**)&wvlo, g_wvlo);
    cudaGetSymbolAddress((void**)&wohi, g_wohi);
    cudaGetSymbolAddress((void**)&wolo, g_wolo);
    cudaGetSymbolAddress((void**)&aqhi, g_qhi);
    cudaGetSymbolAddress((void**)&aqlo, g_qlo);
    cudaGetSymbolAddress((void**)&akhi, g_khi);
    cudaGetSymbolAddress((void**)&aklo, g_klo);
    cudaGetSymbolAddress((void**)&vthi, g_vthi);
    cudaGetSymbolAddress((void**)&vtlo, g_vtlo);

    cudaFuncSetAttribute(gemm_mma, cudaFuncAttributeMaxDynamicSharedMemorySize, 65536);
    cudaFuncSetAttribute(attn_mma, cudaFuncAttributeMaxDynamicSharedMemorySize, 65536);

    const int nx = LSEQ * DIM, nw = DIM * DIM;
    split_kern<<<(nx + 255) / 256, 256>>>(x, xhi, xlo, nx);
    split_kern<<<(nw + 255) / 256, 256>>>(Wq, wqhi, wqlo, nw);
    split_kern<<<(nw + 255) / 256, 256>>>(Wk, wkhi, wklo, nw);
    split_kern<<<(nw + 255) / 256, 256>>>(Wv, wvhi, wvlo, nw);
    split_kern<<<(nw + 255) / 256, 256>>>(Wo, wohi, wolo, nw);

    dim3 gg(DIM / 128, (LSEQ + 127) / 128);
    gemm_mma<<<gg, 256, 65536>>>(xhi, xlo, wqhi, wqlo, bq, pq, LSEQ);
    gemm_mma<<<gg, 256, 65536>>>(xhi, xlo, wkhi, wklo, bk, pk, LSEQ);
    gemm_mma<<<gg, 256, 65536>>>(xhi, xlo, wvhi, wvlo, bv, pv, LSEQ);

    norm_rope<<<LSEQ, 256>>>(pq, pk, aqhi, aqlo, akhi, aklo, gq, gk, freqs,
                             p_h, p_w, p_sf);
    prep_vt<<<dim3((LSEQ + 31) / 32, DIM / 32), 256>>>(pv, vthi, vtlo);

    attn_mma<<<dim3((LSEQ + 63) / 64, NH), 128, 65536>>>(
        aqhi, aqlo, akhi, aklo, vthi, vtlo, po, p_h, p_w, p_local, p_sink);

    split_kern<<<(nx + 255) / 256, 256>>>(po, ohi, olo, nx);
    gemm_mma<<<gg, 256, 65536>>>(ohi, olo, wohi, wolo, bo, out, LSEQ);
}